// round 12
// baseline (speedup 1.0000x reference)
#include <cuda_runtime.h>

// YOLO postprocess: filter(score>0.5) -> sort desc -> greedy NMS(IoU>0.5) -> masked rows.
// x: (1, 84, 8400) f32 channel-major; out: (8400, 5) f32.
//
//   K0 filter (warp-aggregated compaction)
//   K1 rank-by-counting sort + gather (4 threads/key, smem tiles)
//   K2 sparse suppression edge list (64x64 tiles, 4 threads/row, triangle grid)
//   K3 exact greedy fixed-point: byte-status SIMD settle, live-edge ping-pong
//      compaction, fused masked output write, self-reset
//
// Greedy NMS == unique fixed point of:
//   j SUP  iff exists edge (i,j), i<j, i KEEP
//   j KEEP iff every edge (i,j) has i SUP
// Each round the minimum-index unknown row settles => guaranteed convergence.

#define N_IN   8400
#define NSORT  8192
#define FULLW  0xffffffffu
#define ECAP   (1 << 20)      // edge capacity (4 MB scratch; ~25k expected)
#define EBUF   24576          // edges per ping-pong smem buffer (96 KB each)

// status bytes
#define ST_UNK  0x00
#define ST_KEEP 0x01
#define ST_SUP  0x02

// ---------------- global scratch ----------------
__device__ int    g_cnt;      // zero at rest (reset by K3)
__device__ int    g_ecnt;     // zero at rest (reset by K3)
__device__ unsigned long long g_keys[NSORT];
__device__ __align__(16) float4 g_boxes[NSORT];
__device__ float  g_score[NSORT];
__device__ float  g_area[NSORT];
__device__ unsigned g_edges[ECAP];

// ---------------- K0: filter + compact (order canonicalized by K1) --------
extern "C" __global__ void __launch_bounds__(256)
k0_filter_kernel(const float* __restrict__ x)
{
    const int n = blockIdx.x * 256 + threadIdx.x;
    bool pass = false;
    float s = 0.f;
    if (n < N_IN) {
        s = x[4 * N_IN + n];
        pass = (s > 0.5f);
    }
    unsigned m = __ballot_sync(FULLW, pass);
    if (!m) return;
    int lane = threadIdx.x & 31;
    int leader = __ffs(m) - 1;
    int base = 0;
    if (lane == leader) base = atomicAdd(&g_cnt, __popc(m));
    base = __shfl_sync(FULLW, base, leader);
    if (pass) {
        int slot = base + __popc(m & ((1u << lane) - 1));
        if (slot < NSORT) {
            unsigned sb = __float_as_uint(s);
            g_keys[slot] = ((unsigned long long)(~sb) << 32) | (unsigned)n;
        }
    }
}

// ---------------- K1: rank-by-counting sort + gather (4 threads/key) ------
// keys unique (idx in low bits) => rank is an exact permutation.
// key = (~score_bits)<<32 | idx : ascending == descending score, stable ties.
extern "C" __global__ void __launch_bounds__(256)
k1_rank_kernel(const float* __restrict__ x)
{
    __shared__ unsigned long long tile[256];
    __shared__ int srank[64][4];
    const int M = min(g_cnt, NSORT);
    if ((int)(blockIdx.x * 64) >= M) return;          // uniform block early-exit

    const int tid   = threadIdx.x;
    const int key_l = tid & 63;
    const int sub   = tid >> 6;
    const int kslot = blockIdx.x * 64 + key_l;
    const unsigned long long mykey = (kslot < M) ? g_keys[kslot] : ~0ULL;

    int cnt = 0;
    for (int base = 0; base < M; base += 256) {
        int c = base + tid;
        tile[tid] = (c < M) ? g_keys[c] : ~0ULL;      // sentinel never counts
        __syncthreads();
        const unsigned long long* tp = tile + (sub << 6);   // warp-broadcast reads
#pragma unroll 16
        for (int j = 0; j < 64; j++)
            cnt += (tp[j] < mykey);
        __syncthreads();
    }
    srank[key_l][sub] = cnt;
    __syncthreads();

    if (sub == 0 && kslot < M) {
        int rank = srank[key_l][0] + srank[key_l][1]
                 + srank[key_l][2] + srank[key_l][3];
        int idx = (int)(unsigned)mykey;
        float X1 = x[idx];
        float Y1 = x[N_IN + idx];
        float X2 = x[2 * N_IN + idx];
        float Y2 = x[3 * N_IN + idx];
        g_boxes[rank] = make_float4(X1, Y1, X2, Y2);
        g_score[rank] = __uint_as_float(~(unsigned)(mykey >> 32));
        g_area[rank]  = (X2 - X1) * (Y2 - Y1);
    }
}

// ---------------- K2: sparse edges (64x64 tiles, 4 threads/row) -----------
// Triangle-linear grid (ty <= tx); edge (i,j), i<j, packed (i<<13)|j when
//   IoU > 0.5 <=> 3*inter > area_i + area_j + 1e-9 (denominator always > 0).
#define NCT64   (NSORT / 64)                     // 128
#define K2_GRID (NCT64 * (NCT64 + 1) / 2)        // 8256

extern "C" __global__ void __launch_bounds__(256)
k2_edges_kernel()
{
    // linear -> (ty <= tx) triangle decode
    const int L = blockIdx.x;
    int tx = (int)((sqrtf(8.0f * (float)L + 1.0f) - 1.0f) * 0.5f);
    while ((tx + 1) * (tx + 2) / 2 <= L) tx++;
    while (tx * (tx + 1) / 2 > L) tx--;
    const int ty = L - tx * (tx + 1) / 2;

    const int M = min(g_cnt, NSORT);
    const int nct = (M + 63) >> 6;
    if (ty >= nct || tx >= nct) return;

    __shared__ float4 cb[64];
    __shared__ float  ca[64];
    __shared__ unsigned ebuf[4096];     // worst case: full 64x64 tile
    __shared__ int ec, gbase;
    const int t  = threadIdx.x;
    if (t == 0) ec = 0;
    const int j0 = tx << 6;
    if (t < 64) {
        int jg = j0 + t;
        if (jg < M) { cb[t] = g_boxes[jg]; ca[t] = g_area[jg]; }
        else        { cb[t] = make_float4(0, 0, 0, 0); ca[t] = 1e30f; }
    }
    __syncthreads();

    const int row = t >> 2, sub = t & 3;
    const int i   = (ty << 6) + row;
    if (i < M) {
        const float4 b  = g_boxes[i];
        const float  sA = g_area[i] + 1e-9f;
        const int    c1 = min((sub << 4) + 16, M - j0);
#pragma unroll 4
        for (int c = sub << 4; c < c1; c++) {
            int j = j0 + c;
            if (j > i) {
                float4 q = cb[c];
                float iw = fminf(b.z, q.z) - fmaxf(b.x, q.x);
                float ih = fminf(b.w, q.w) - fmaxf(b.y, q.y);
                float inter = fmaxf(iw, 0.f) * fmaxf(ih, 0.f);
                if (3.0f * inter > sA + ca[c]) {
                    int p = atomicAdd(&ec, 1);
                    ebuf[p] = ((unsigned)i << 13) | (unsigned)j;
                }
            }
        }
    }
    __syncthreads();
    if (t == 0 && ec > 0) gbase = atomicAdd(&g_ecnt, ec);
    __syncthreads();
    for (int p = t; p < ec; p += 256) {
        int gp = gbase + p;
        if (gp < ECAP) g_edges[gp] = ebuf[p];
    }
}

// ---------------- K3: byte-status fixed point + fused output --------------
// statB : 0=UNK, 1=KEEP, 2=SUP. nsupB/unkpB: 0xFF marks (plain stores, benign
// same-value races). nsupB never reset (a marked row settles that round);
// unkpB reset per round. Settle is SIMD-in-register over u64 (8 rows/thread).
#define K3_SMEM (2 * EBUF * 4)     // 192 KB ping-pong edge buffers

extern "C" __global__ void __launch_bounds__(1024, 1)
k3_fixed_kernel(float* __restrict__ out)
{
    extern __shared__ unsigned se[];                  // [2][EBUF]
    __shared__ __align__(8) unsigned char statB[NSORT];
    __shared__ __align__(8) unsigned char nsupB[NSORT];
    __shared__ __align__(8) unsigned char unkpB[NSORT];
    __shared__ int notdone, livecnt;
    const int M   = min(g_cnt, NSORT);
    const int tid = threadIdx.x, lane = tid & 31;
    int E = g_ecnt; if (E > ECAP) E = ECAP;
    const int Eover = (E > EBUF) ? (E - EBUF) : 0;    // stays in global, uncompacted

    unsigned* cur = se;
    unsigned* nxt = se + EBUF;
    int curN = min(E, EBUF);

    for (int e = tid; e < curN; e += 1024) cur[e] = g_edges[e];
    ((unsigned long long*)statB)[tid] = 0ULL;         // 1024 u64 = 8192 bytes
    ((unsigned long long*)nsupB)[tid] = 0ULL;
    __syncthreads();

    for (int round = 0; round < NSORT; round++) {
        ((unsigned long long*)unkpB)[tid] = 0ULL;
        if (tid == 0) { notdone = 0; livecnt = 0; }
        __syncthreads();

        // classify; returns live (both endpoints unknown)
        auto classify = [&](unsigned ed) -> bool {
            int i = (int)(ed >> 13), j = (int)(ed & 8191u);
            if (statB[j]) return false;               // j settled
            unsigned char si = statB[i];
            if (si == ST_KEEP) { nsupB[j] = 0xFF; return false; }
            if (si == ST_SUP)  return false;          // vacuous edge
            unkpB[j] = 0xFF;                          // unknown pred
            return true;
        };

        // smem edges: classify + warp-aggregated compaction into nxt
        for (int e0 = 0; e0 < curN; e0 += 1024) {
            int e = e0 + tid;
            bool act = (e < curN);
            unsigned ed = act ? cur[e] : 0u;
            bool live = act && classify(ed);
            unsigned m = __ballot_sync(FULLW, live);
            if (m) {
                int leader = __ffs(m) - 1;
                int base = 0;
                if (lane == leader) base = atomicAdd(&livecnt, __popc(m));
                base = __shfl_sync(FULLW, base, leader);
                if (live) nxt[base + __popc(m & ((1u << lane) - 1))] = ed;
            }
        }
        // overflow edges: classify only (never compacted)
        for (int e = tid; e < Eover; e += 1024) classify(g_edges[EBUF + e]);
        __syncthreads();

        // SIMD settle: thread owns bytes [tid*8, tid*8+8)
        {
            int base = tid << 3;
            unsigned long long s = ((unsigned long long*)statB)[tid];
            unsigned long long n = ((unsigned long long*)nsupB)[tid];
            unsigned long long u = ((unsigned long long*)unkpB)[tid];
            // valid-byte mask for rows < M
            unsigned long long vm;
            if (base + 8 <= M)      vm = ~0ULL;
            else if (base >= M)     vm = 0ULL;
            else                    vm = (1ULL << ((M - base) << 3)) - 1ULL;
            // byte-wise stat==0 mask
            unsigned zlo = __vcmpeq4((unsigned)s, 0u);
            unsigned zhi = __vcmpeq4((unsigned)(s >> 32), 0u);
            unsigned long long z = ((unsigned long long)zhi << 32) | zlo;
            z &= vm;
            unsigned long long supNew  = z & n;
            unsigned long long keepNew = z & ~n & ~u;
            unsigned long long remain  = z & ~n & u;
            if (supNew | keepNew) {
                s |= (supNew  & 0x0202020202020202ULL)
                   | (keepNew & 0x0101010101010101ULL);
                ((unsigned long long*)statB)[tid] = s;
            }
            if (remain) notdone = 1;                  // benign race
        }
        __syncthreads();
        if (!notdone) break;
        curN = livecnt;
        unsigned* tmp = cur; cur = nxt; nxt = tmp;
        __syncthreads();     // livecnt read complete before next-round reset
    }

    // fused masked output write
    for (int r = tid; r < N_IN; r += 1024) {
        if (r < M) {
            float m = (statB[r] == ST_KEEP) ? 1.0f : 0.0f;
            float4 b = g_boxes[r];
            out[r * 5 + 0] = b.x * m;
            out[r * 5 + 1] = b.y * m;
            out[r * 5 + 2] = b.z * m;
            out[r * 5 + 3] = b.w * m;
            out[r * 5 + 4] = g_score[r] * m;
        } else {
            out[r * 5 + 0] = 0.f;
            out[r * 5 + 1] = 0.f;
            out[r * 5 + 2] = 0.f;
            out[r * 5 + 3] = 0.f;
            out[r * 5 + 4] = 0.f;
        }
    }

    // restore zero-invariants for next call / graph replay
    if (tid == 0) { g_cnt = 0; g_ecnt = 0; }
}

// ---------------- launcher ----------------
extern "C" void kernel_launch(void* const* d_in, const int* in_sizes, int n_in,
                              void* d_out, int out_size)
{
    (void)in_sizes; (void)n_in; (void)out_size;
    const float* x = (const float*)d_in[0];
    float* out = (float*)d_out;

    static bool init_done = false;
    if (!init_done) {
        cudaFuncSetAttribute(k3_fixed_kernel,
                             cudaFuncAttributeMaxDynamicSharedMemorySize, K3_SMEM);
        init_done = true;
    }

    k0_filter_kernel<<<(N_IN + 255) / 256, 256>>>(x);
    k1_rank_kernel<<<NSORT / 64, 256>>>(x);
    k2_edges_kernel<<<K2_GRID, 256>>>();
    k3_fixed_kernel<<<1, 1024, K3_SMEM>>>(out);
}